// round 17
// baseline (speedup 1.0000x reference)
#include <cuda_runtime.h>
#include <cuda_fp16.h>
#include <cstdint>

#define D 128
#define N_NODES_MAX 50000
#define E_MAX 600000
#define SLOT 48          // fixed bucket capacity per node (P(deg>48) ~ 1e-16)
#define OVF_CAP 8192
#define AS_STRIDE 136    // fp16 elems per smem row (272B -> conflict-free ldmatrix)
#define HS_STRIDE 132    // fp16 elems per smem row for h staging (264B, 8B aligned)

// Scratch (device globals — no allocation allowed)
__device__ __half2 g_hh[N_NODES_MAX * (D / 2)];  // h = x @ W^T, fp16 (gather payload)
__device__ float g_ssrc[N_NODES_MAX];
__device__ float g_sdst[N_NODES_MAX];
__device__ int   g_cnt[N_NODES_MAX];        // in-degree; ZERO invariant (module load;
                                            // re-zeroed by agg_ln each launch)
__device__ int   g_bk[N_NODES_MAX * SLOT];  // bucketed src ids
__device__ int   g_ovf_cnt;                 // overflow count (re-zeroed by agg_ln)
__device__ int   g_ovf_src[OVF_CAP];
__device__ int   g_ovf_dst[OVF_CAP];

// ---------------- mma.sync helpers ----------------
__device__ __forceinline__ void ldm4(unsigned int& r0, unsigned int& r1,
                                     unsigned int& r2, unsigned int& r3,
                                     const void* p) {
    unsigned int addr = (unsigned int)__cvta_generic_to_shared(p);
    asm volatile("ldmatrix.sync.aligned.m8n8.x4.shared.b16 {%0,%1,%2,%3}, [%4];"
                 : "=r"(r0), "=r"(r1), "=r"(r2), "=r"(r3) : "r"(addr));
}
__device__ __forceinline__ void mma16816(float* c, const unsigned int* a,
                                         const unsigned int* b) {
    asm volatile("mma.sync.aligned.m16n8k16.row.col.f32.f16.f16.f32 "
                 "{%0,%1,%2,%3}, {%4,%5,%6,%7}, {%8,%9}, {%0,%1,%2,%3};"
                 : "+f"(c[0]), "+f"(c[1]), "+f"(c[2]), "+f"(c[3])
                 : "r"(a[0]), "r"(a[1]), "r"(a[2]), "r"(a[3]), "r"(b[0]), "r"(b[1]));
}

// ---------------------------------------------------------------------------
// 1) Bucket edges directly: rank = atomicAdd(cnt[dst]); bk[dst*SLOT+rank]=src.
// ---------------------------------------------------------------------------
__device__ __forceinline__ void bucket_one(int src, int dst) {
    int r = atomicAdd(&g_cnt[dst], 1);
    if (r < SLOT) {
        g_bk[dst * SLOT + r] = src;
    } else {
        int p = atomicAdd(&g_ovf_cnt, 1);
        if (p < OVF_CAP) { g_ovf_src[p] = src; g_ovf_dst[p] = dst; }
    }
}
__global__ void bucket_kernel(const int* __restrict__ ei, int E) {
    int t = blockIdx.x * blockDim.x + threadIdx.x;
    int e = t * 4;
    if (e + 4 <= E) {
        int4 s = *(const int4*)&ei[e];
        int4 d = *(const int4*)&ei[E + e];
        bucket_one(s.x, d.x);
        bucket_one(s.y, d.y);
        bucket_one(s.z, d.z);
        bucket_one(s.w, d.w);
    } else {
        for (int k = e; k < E; k++) bucket_one(ei[k], ei[E + k]);
    }
}

// ---------------------------------------------------------------------------
// 2) GEMM h = x @ W^T on tensor cores. 512 threads/CTA, 16 warps in a 4x4
//    grid, warp tile 32x32 -> 32 acc regs/thread (~100 total) -> 16 warps/SM
//    resident (2x the latency hiding of the 256-thread version).
// ---------------------------------------------------------------------------
__global__ __launch_bounds__(512, 1) void gemm_mma_kernel(
    const float* __restrict__ x, const float* __restrict__ W,
    const float* __restrict__ a, int N)
{
    extern __shared__ __half sm2[];
    __half* As = sm2;                               // 128 x AS_STRIDE
    __half* Bs = sm2 + 128 * AS_STRIDE;             // 128 x AS_STRIDE
    float* a_s = (float*)(sm2 + 2 * 128 * AS_STRIDE);  // 256 floats
    const int tid = threadIdx.x;
    const int row0 = blockIdx.x * 128;

    if (tid < 256) a_s[tid] = a[tid];

    const float4* x4 = (const float4*)x;
    const float4* W4 = (const float4*)W;
    #pragma unroll
    for (int i = 0; i < 8; i++) {
        int idx = tid + i * 512;          // 0..4095
        int k4 = idx & 31, r = idx >> 5;
        float4 v = (row0 + r < N) ? x4[(row0 + r) * 32 + k4]
                                  : make_float4(0.f, 0.f, 0.f, 0.f);
        *(__half2*)&As[r * AS_STRIDE + k4 * 4]     = __floats2half2_rn(v.x, v.y);
        *(__half2*)&As[r * AS_STRIDE + k4 * 4 + 2] = __floats2half2_rn(v.z, v.w);
        float4 w = W4[idx];
        *(__half2*)&Bs[r * AS_STRIDE + k4 * 4]     = __floats2half2_rn(w.x, w.y);
        *(__half2*)&Bs[r * AS_STRIDE + k4 * 4 + 2] = __floats2half2_rn(w.z, w.w);
    }
    __syncthreads();

    const int wid = tid >> 5, lane = tid & 31;
    const int m_base = (wid & 3) * 32;
    const int n_base = (wid >> 2) * 32;

    float acc[2][4][4];
    #pragma unroll
    for (int tm = 0; tm < 2; tm++)
        #pragma unroll
        for (int tn = 0; tn < 4; tn++)
            #pragma unroll
            for (int c = 0; c < 4; c++) acc[tm][tn][c] = 0.f;

    const int lmA = (lane & 7) + ((lane >> 3) & 1) * 8;
    const int lkA = (lane >> 4) * 8;
    const int lnB = (lane & 7) + (lane >> 4) * 8;
    const int lkB = ((lane >> 3) & 1) * 8;

    #pragma unroll
    for (int ks = 0; ks < 8; ks++) {
        int k0 = ks * 16;
        unsigned int af[2][4];
        #pragma unroll
        for (int tm = 0; tm < 2; tm++)
            ldm4(af[tm][0], af[tm][1], af[tm][2], af[tm][3],
                 &As[(m_base + tm * 16 + lmA) * AS_STRIDE + k0 + lkA]);
        unsigned int bf[4][2];
        #pragma unroll
        for (int tp = 0; tp < 2; tp++) {
            unsigned int r0, r1, r2, r3;
            ldm4(r0, r1, r2, r3,
                 &Bs[(n_base + tp * 16 + lnB) * AS_STRIDE + k0 + lkB]);
            bf[tp * 2][0] = r0; bf[tp * 2][1] = r1;
            bf[tp * 2 + 1][0] = r2; bf[tp * 2 + 1][1] = r3;
        }
        #pragma unroll
        for (int tm = 0; tm < 2; tm++)
            #pragma unroll
            for (int tn = 0; tn < 4; tn++)
                mma16816(acc[tm][tn], af[tm], bf[tn]);
    }

    __syncthreads();
    __half* Hs = As;   // 128 x HS_STRIDE
    #pragma unroll
    for (int tm = 0; tm < 2; tm++) {
        int m = m_base + tm * 16 + (lane >> 2);
        #pragma unroll
        for (int tn = 0; tn < 4; tn++) {
            int n = n_base + tn * 8 + (lane & 3) * 2;
            *(__half2*)&Hs[m * HS_STRIDE + n] =
                __floats2half2_rn(acc[tm][tn][0], acc[tm][tn][1]);
            *(__half2*)&Hs[(m + 8) * HS_STRIDE + n] =
                __floats2half2_rn(acc[tm][tn][2], acc[tm][tn][3]);
        }
    }
    __syncthreads();

    // Coalesced fp16 h writeback: 128 rows x 32 uint2 = 4096 over 512 threads
    #pragma unroll
    for (int i = 0; i < 8; i++) {
        int idx = tid + i * 512;
        int c = idx & 31, r = idx >> 5;
        if (row0 + r < N) {
            uint2 v = *(uint2*)&Hs[r * HS_STRIDE + c * 4];
            *(uint2*)&g_hh[(row0 + r) * 64 + c * 2] = v;
        }
    }

    // Scores: threads 0-127 -> s_src rows, 128-255 -> s_dst rows.
    if (tid < 256) {
        int r = tid & 127;
        const float* av = a_s + ((tid >= 128) ? 128 : 0);
        if (row0 + r < N) {
            float s = 0.f;
            #pragma unroll 8
            for (int j = 0; j < 64; j++) {
                float2 f = __half22float2(*(__half2*)&Hs[r * HS_STRIDE + j * 2]);
                s += f.x * av[2 * j] + f.y * av[2 * j + 1];
            }
            if (tid >= 128) g_sdst[row0 + r] = s;
            else            g_ssrc[row0 + r] = s;
        }
    }
}

// ---------------------------------------------------------------------------
// 3) Fused aggregate + residual + LayerNorm (unchanged from R16).
// ---------------------------------------------------------------------------
__global__ __launch_bounds__(256) void agg_ln_kernel(
    const float* __restrict__ x, const float* __restrict__ gamma,
    const float* __restrict__ beta, float* __restrict__ out, int N)
{
    int gw = (blockIdx.x * blockDim.x + threadIdx.x) >> 5;
    int lane = threadIdx.x & 31;
    if (gw >= N) return;
    int deg = g_cnt[gw];
    int start = gw * SLOT;
    int end = start + min(deg, SLOT);
    float sdst = g_sdst[gw];

    const __half2* hh = g_hh;
    float a0 = 0.f, a1 = 0.f, a2 = 0.f, a3 = 0.f, z = 0.f;
    int e = start;
    for (; e + 4 <= end; e += 4) {
        int s0 = g_bk[e + 0];
        int s1 = g_bk[e + 1];
        int s2 = g_bk[e + 2];
        int s3 = g_bk[e + 3];
        uint2 r0 = *(const uint2*)&hh[s0 * (D / 2) + lane * 2];
        uint2 r1 = *(const uint2*)&hh[s1 * (D / 2) + lane * 2];
        uint2 r2 = *(const uint2*)&hh[s2 * (D / 2) + lane * 2];
        uint2 r3 = *(const uint2*)&hh[s3 * (D / 2) + lane * 2];
        float v0 = g_ssrc[s0] + sdst; v0 = v0 > 0.f ? v0 : 0.2f * v0;
        float v1 = g_ssrc[s1] + sdst; v1 = v1 > 0.f ? v1 : 0.2f * v1;
        float v2 = g_ssrc[s2] + sdst; v2 = v2 > 0.f ? v2 : 0.2f * v2;
        float v3 = g_ssrc[s3] + sdst; v3 = v3 > 0.f ? v3 : 0.2f * v3;
        float e0 = __expf(v0), e1 = __expf(v1), e2 = __expf(v2), e3 = __expf(v3);
        z += (e0 + e1) + (e2 + e3);
        float2 f0a = __half22float2(*(__half2*)&r0.x), f0b = __half22float2(*(__half2*)&r0.y);
        float2 f1a = __half22float2(*(__half2*)&r1.x), f1b = __half22float2(*(__half2*)&r1.y);
        float2 f2a = __half22float2(*(__half2*)&r2.x), f2b = __half22float2(*(__half2*)&r2.y);
        float2 f3a = __half22float2(*(__half2*)&r3.x), f3b = __half22float2(*(__half2*)&r3.y);
        a0 += e0 * f0a.x + e1 * f1a.x + e2 * f2a.x + e3 * f3a.x;
        a1 += e0 * f0a.y + e1 * f1a.y + e2 * f2a.y + e3 * f3a.y;
        a2 += e0 * f0b.x + e1 * f1b.x + e2 * f2b.x + e3 * f3b.x;
        a3 += e0 * f0b.y + e1 * f1b.y + e2 * f2b.y + e3 * f3b.y;
    }
    for (; e < end; e++) {
        int s0 = g_bk[e];
        uint2 r0 = *(const uint2*)&hh[s0 * (D / 2) + lane * 2];
        float v0 = g_ssrc[s0] + sdst; v0 = v0 > 0.f ? v0 : 0.2f * v0;
        float e0 = __expf(v0);
        z += e0;
        float2 f0a = __half22float2(*(__half2*)&r0.x), f0b = __half22float2(*(__half2*)&r0.y);
        a0 += e0 * f0a.x; a1 += e0 * f0a.y; a2 += e0 * f0b.x; a3 += e0 * f0b.y;
    }
    if (deg > SLOT) {
        int oc = g_ovf_cnt;
        if (oc > OVF_CAP) oc = OVF_CAP;
        for (int i = 0; i < oc; i++) {
            if (g_ovf_dst[i] == gw) {
                int s0 = g_ovf_src[i];
                uint2 r0 = *(const uint2*)&hh[s0 * (D / 2) + lane * 2];
                float v0 = g_ssrc[s0] + sdst; v0 = v0 > 0.f ? v0 : 0.2f * v0;
                float e0 = __expf(v0);
                z += e0;
                float2 f0a = __half22float2(*(__half2*)&r0.x);
                float2 f0b = __half22float2(*(__half2*)&r0.y);
                a0 += e0 * f0a.x; a1 += e0 * f0a.y; a2 += e0 * f0b.x; a3 += e0 * f0b.y;
            }
        }
    }
    float invz = (deg > 0) ? 1.f / z : 0.f;

    if (lane == 0) {
        g_cnt[gw] = 0;
        if (gw == 0) g_ovf_cnt = 0;
    }

    float4 xv = *(const float4*)&x[gw * D + lane * 4];
    float y0 = a0 * invz + xv.x, y1 = a1 * invz + xv.y;
    float y2 = a2 * invz + xv.z, y3 = a3 * invz + xv.w;

    float s = y0 + y1 + y2 + y3;
    #pragma unroll
    for (int off = 16; off > 0; off >>= 1) s += __shfl_xor_sync(0xffffffffu, s, off);
    float mean = s * (1.f / 128.f);
    float d0 = y0 - mean, d1 = y1 - mean, d2 = y2 - mean, d3 = y3 - mean;
    float q = d0 * d0 + d1 * d1 + d2 * d2 + d3 * d3;
    #pragma unroll
    for (int off = 16; off > 0; off >>= 1) q += __shfl_xor_sync(0xffffffffu, q, off);
    float inv = rsqrtf(q * (1.f / 128.f) + 1e-5f);

    float4 gv = *(const float4*)&gamma[lane * 4];
    float4 bv = *(const float4*)&beta[lane * 4];
    float4 o;
    o.x = d0 * inv * gv.x + bv.x;
    o.y = d1 * inv * gv.y + bv.y;
    o.z = d2 * inv * gv.z + bv.z;
    o.w = d3 * inv * gv.w + bv.w;
    *(float4*)&out[gw * D + lane * 4] = o;
}

// ---------------------------------------------------------------------------
extern "C" void kernel_launch(void* const* d_in, const int* in_sizes, int n_in,
                              void* d_out, int out_size) {
    const float* x     = (const float*)d_in[0];
    const int*   ei    = (const int*)d_in[1];
    const float* W     = (const float*)d_in[2];
    const float* a     = (const float*)d_in[3];
    const float* gamma = (const float*)d_in[4];
    const float* beta  = (const float*)d_in[5];
    float* out = (float*)d_out;

    int N = in_sizes[0] / D;
    int E = in_sizes[1] / 2;
    int e4blocks = ((E + 3) / 4 + 255) / 256;

    static cudaStream_t s_side = nullptr;
    static cudaEvent_t ev_fork = nullptr, ev_join = nullptr;
    if (!s_side) {
        cudaStreamCreateWithFlags(&s_side, cudaStreamNonBlocking);
        cudaEventCreateWithFlags(&ev_fork, cudaEventDisableTiming);
        cudaEventCreateWithFlags(&ev_join, cudaEventDisableTiming);
    }

    int smem = 2 * 128 * AS_STRIDE * (int)sizeof(__half) + 256 * (int)sizeof(float);
    cudaFuncSetAttribute(gemm_mma_kernel, cudaFuncAttributeMaxDynamicSharedMemorySize, smem);

    cudaEventRecord(ev_fork, 0);
    cudaStreamWaitEvent(s_side, ev_fork, 0);
    bucket_kernel<<<e4blocks, 256, 0, s_side>>>(ei, E);
    cudaEventRecord(ev_join, s_side);

    gemm_mma_kernel<<<(N + 127) / 128, 512, smem>>>(x, W, a, N);

    cudaStreamWaitEvent(0, ev_join, 0);
    agg_ln_kernel<<<(N * 32 + 255) / 256, 256>>>(x, gamma, beta, out, N);
}